// round 11
// baseline (speedup 1.0000x reference)
#include <cuda_runtime.h>
#include <cuda_fp16.h>
#include <mma.h>
#include <math.h>

using namespace nvcuda;

#define NMAX 50000
#define NPAD 50176                 // padded rows so wmma tail stores stay in-bounds
#define EMAX 1600000
#define FIN  128
#define FOUT 64
#define ALPHA 0.2f

// ---------------- scratch (device globals; no allocation) ----------------
__device__ float g_h[NPAD * FOUT];       // h = input @ W (fp32; padded tail)
__device__ float g_hprime[NMAX * FOUT];  // segment sum accumulator
__device__ float g_hcol[NMAX];           // h . a1l  (= input . (W a1l))
__device__ float g_ha2r[NMAX];           // h . a2r
__device__ float g_pha1r[NMAX];          // p_h . (W a1r)
__device__ float g_nha2l[NMAX];          // new_h . (W a2l)
__device__ float g_ecsm[NMAX];           // edge_col_e -> ex -> softmax result
__device__ float g_segmax[NMAX];
__device__ float g_segsum[NMAX];
__device__ float g_erowsum[NMAX];
__device__ float g_edge_e[EMAX];
__device__ float g_v1[FIN], g_v2[FIN], g_v3[FIN], g_v4[FIN];

// ---------------- zeroing (merged; graph-replay safe reset) ----------------
__global__ void k_zero(int n) {
    int i = blockIdx.x * blockDim.x + threadIdx.x;
    if (i < n * (FOUT / 4))
        ((float4*)g_hprime)[i] = make_float4(0.f, 0.f, 0.f, 0.f);
    if (i < n) {
        g_segmax[i] = 0.f;
        g_segsum[i] = 0.f;
        g_erowsum[i] = 0.f;
    }
}

// ---------------- small vectors: v = W @ a-halves ----------------
__global__ void k_vec(const float* __restrict__ W,
                      const float* __restrict__ a1,
                      const float* __restrict__ a2) {
    int k = threadIdx.x;  // 128 threads
    float s1 = 0.f, s2 = 0.f, s3 = 0.f, s4 = 0.f;
#pragma unroll 8
    for (int j = 0; j < FOUT; j++) {
        float w = W[k * FOUT + j];
        s1 += w * a1[j];
        s2 += w * a1[FOUT + j];
        s3 += w * a2[j];
        s4 += w * a2[FOUT + j];
    }
    g_v1[k] = s1; g_v2[k] = s2; g_v3[k] = s3; g_v4[k] = s4;
}

// ---------------- per-row dot products: 2 rows per warp ----------------
__global__ void k_dots(const float* __restrict__ X,
                       const float* __restrict__ P,
                       const float* __restrict__ NH, int n) {
    int warp = (blockIdx.x * blockDim.x + threadIdx.x) >> 5;
    int lane = threadIdx.x & 31;
    int r0 = warp * 2;
    if (r0 >= n) return;
    int r1 = r0 + 1 < n ? r0 + 1 : r0;
    float4 xv0 = ((const float4*)(X + (long)r0 * FIN))[lane];
    float4 pv0 = ((const float4*)(P + (long)r0 * FIN))[lane];
    float4 nv0 = ((const float4*)(NH + (long)r0 * FIN))[lane];
    float4 xv1 = ((const float4*)(X + (long)r1 * FIN))[lane];
    float4 pv1 = ((const float4*)(P + (long)r1 * FIN))[lane];
    float4 nv1 = ((const float4*)(NH + (long)r1 * FIN))[lane];
    float4 v1 = ((const float4*)g_v1)[lane];
    float4 v2 = ((const float4*)g_v2)[lane];
    float4 v3 = ((const float4*)g_v3)[lane];
    float4 v4 = ((const float4*)g_v4)[lane];
    float a0 = xv0.x * v1.x + xv0.y * v1.y + xv0.z * v1.z + xv0.w * v1.w;
    float b0 = xv0.x * v4.x + xv0.y * v4.y + xv0.z * v4.z + xv0.w * v4.w;
    float c0 = pv0.x * v2.x + pv0.y * v2.y + pv0.z * v2.z + pv0.w * v2.w;
    float d0 = nv0.x * v3.x + nv0.y * v3.y + nv0.z * v3.z + nv0.w * v3.w;
    float a1 = xv1.x * v1.x + xv1.y * v1.y + xv1.z * v1.z + xv1.w * v1.w;
    float b1 = xv1.x * v4.x + xv1.y * v4.y + xv1.z * v4.z + xv1.w * v4.w;
    float c1 = pv1.x * v2.x + pv1.y * v2.y + pv1.z * v2.z + pv1.w * v2.w;
    float d1 = nv1.x * v3.x + nv1.y * v3.y + nv1.z * v3.z + nv1.w * v3.w;
#pragma unroll
    for (int o = 16; o > 0; o >>= 1) {
        a0 += __shfl_down_sync(0xFFFFFFFFu, a0, o);
        b0 += __shfl_down_sync(0xFFFFFFFFu, b0, o);
        c0 += __shfl_down_sync(0xFFFFFFFFu, c0, o);
        d0 += __shfl_down_sync(0xFFFFFFFFu, d0, o);
        a1 += __shfl_down_sync(0xFFFFFFFFu, a1, o);
        b1 += __shfl_down_sync(0xFFFFFFFFu, b1, o);
        c1 += __shfl_down_sync(0xFFFFFFFFu, c1, o);
        d1 += __shfl_down_sync(0xFFFFFFFFu, d1, o);
    }
    if (lane == 0) {
        g_hcol[r0] = a0; g_ha2r[r0] = b0; g_pha1r[r0] = c0; g_nha2l[r0] = d0;
        if (r1 != r0) {
            g_hcol[r1] = a1; g_ha2r[r1] = b1; g_pha1r[r1] = c1; g_nha2l[r1] = d1;
        }
    }
}

// ---------------- GEMM: h = input @ W via fp16 tensor cores ----------------
// 512 threads = 16 warps (8 row-groups x 2 col-groups). Block tile 128x64,
// K chunked by 64. Warp tile 16x32 (2 fragments) -> low regs, occ up.
#define XS_LD 72   // 64 + 8 pad halves; 144 B row stride (16B multiple)
#define WS_LD 72
__global__ void __launch_bounds__(512)
k_gemm(const float* __restrict__ X, const float* __restrict__ W, int n) {
    __shared__ __half Xs[128][XS_LD];  // 18.4 KB  [row][k]
    __shared__ __half Ws[64][WS_LD];   //  9.2 KB  [k][col]
    int tid = threadIdx.x;
    int warp = tid >> 5;
    int wr = warp >> 1;    // 0..7 -> rows wr*16..+15
    int wc = warp & 1;     // 0..1 -> cols wc*32..+31
    long row0 = (long)blockIdx.x * 128;

    wmma::fragment<wmma::accumulator, 16, 16, 16, float> acc[2];
    wmma::fill_fragment(acc[0], 0.f);
    wmma::fill_fragment(acc[1], 0.f);

    for (int kb = 0; kb < FIN; kb += 64) {
        // stage X chunk: 128 rows x 64 k = 2048 float4, 4 per thread
#pragma unroll
        for (int i = 0; i < 4; i++) {
            int idx = tid + i * 512;       // 0..2047
            int r = idx >> 4;
            int k0 = (idx & 15) * 4;
            long row = row0 + r;
            __half2 h0, h1;
            if (row < n) {
                float4 v = *(const float4*)(X + row * FIN + kb + k0);
                h0 = __floats2half2_rn(v.x, v.y);
                h1 = __floats2half2_rn(v.z, v.w);
            } else {
                h0 = __floats2half2_rn(0.f, 0.f);
                h1 = h0;
            }
            __half2* dst = (__half2*)&Xs[r][k0];
            dst[0] = h0; dst[1] = h1;
        }
        // stage W chunk: 64 k x 64 c = 1024 float4, 2 per thread
#pragma unroll
        for (int i = 0; i < 2; i++) {
            int idx = tid + i * 512;       // 0..1023
            int k = idx >> 4;
            int c0 = (idx & 15) * 4;
            float4 v = *(const float4*)(W + (long)(kb + k) * FOUT + c0);
            __half2* dst = (__half2*)&Ws[k][c0];
            dst[0] = __floats2half2_rn(v.x, v.y);
            dst[1] = __floats2half2_rn(v.z, v.w);
        }
        __syncthreads();
#pragma unroll
        for (int k16 = 0; k16 < 64; k16 += 16) {
            wmma::fragment<wmma::matrix_a, 16, 16, 16, __half, wmma::row_major> a;
            wmma::fragment<wmma::matrix_b, 16, 16, 16, __half, wmma::row_major> b0, b1;
            wmma::load_matrix_sync(a, &Xs[wr * 16][k16], XS_LD);
            wmma::load_matrix_sync(b0, &Ws[k16][wc * 32], WS_LD);
            wmma::load_matrix_sync(b1, &Ws[k16][wc * 32 + 16], WS_LD);
            wmma::mma_sync(acc[0], a, b0, acc[0]);
            wmma::mma_sync(acc[1], a, b1, acc[1]);
        }
        __syncthreads();
    }
    // store (padding rows absorb the tail; g_h has NPAD rows)
#pragma unroll
    for (int j = 0; j < 2; j++) {
        float* dst = g_h + (row0 + wr * 16) * FOUT + wc * 32 + j * 16;
        wmma::store_matrix_sync(dst, acc[j], FOUT, wmma::mem_row_major);
    }
}

// ---------------- column softmax passes ----------------
__global__ void k_col1(const int* __restrict__ edge_col0,
                       const int* __restrict__ row_i, int n) {
    int i = blockIdx.x * blockDim.x + threadIdx.x;
    if (i >= n) return;
    float cs = g_hcol[edge_col0[i]] + g_pha1r[i];
    float lr = cs > 0.f ? cs : ALPHA * cs;
    float e = expf(-lr);
    g_ecsm[i] = e;
    atomicMax((int*)&g_segmax[row_i[i]], __float_as_int(e));  // e > 0 always
}
__global__ void k_col2(const int* __restrict__ row_i, int n) {
    int i = blockIdx.x * blockDim.x + threadIdx.x;
    if (i >= n) return;
    float ex = expf(g_ecsm[i] - g_segmax[row_i[i]]);
    g_ecsm[i] = ex;
    atomicAdd(&g_segsum[row_i[i]], ex);
}
__global__ void k_col3(const int* __restrict__ row_i, int n) {
    int i = blockIdx.x * blockDim.x + threadIdx.x;
    if (i >= n) return;
    g_ecsm[i] = g_ecsm[i] / (g_segsum[row_i[i]] + 1e-16f);
}

// ---------------- fused edge kernel: score + rowsum + scatter ----------------
// 16 threads per edge. All lanes compute ee redundantly (SIMT: same warp
// instructions either way); lane t==0 writes edge_e and the erowsum atomic.
// Scatter: float4 gather + red.global.add.v4.f32 (proven R1 shape, LTS-bound).
__global__ void k_edge(const int* __restrict__ edge0,
                       const int* __restrict__ edge1,
                       const int* __restrict__ row_resort, int E) {
    int e = (blockIdx.x * blockDim.x + threadIdx.x) >> 4;
    int t = threadIdx.x & 15;
    if (e >= E) return;
    int dst = edge0[e], src = edge1[e];
    int rr = row_resort[e];
    float rs = g_nha2l[rr] + g_ha2r[src];
    float lr = rs > 0.f ? rs : ALPHA * rs;
    float ee = expf(-lr) * g_ecsm[rr];
    if (t == 0) {
        g_edge_e[e] = ee;
        atomicAdd(&g_erowsum[dst], ee);
    }
    float4 hv = *(const float4*)(g_h + (long)src * FOUT + t * 4);
    float4 r;
    r.x = ee * hv.x; r.y = ee * hv.y; r.z = ee * hv.z; r.w = ee * hv.w;
    float* dp = g_hprime + (long)dst * FOUT + t * 4;
    asm volatile("red.global.add.v4.f32 [%0], {%1, %2, %3, %4};"
                 :: "l"(__cvta_generic_to_global(dp)),
                    "f"(r.x), "f"(r.y), "f"(r.z), "f"(r.w)
                 : "memory");
}

// ---------------- finalize: out = elu(h_prime / e_rowsum) ----------------
__global__ void k_final(float* __restrict__ out, int n) {
    int i4 = blockIdx.x * blockDim.x + threadIdx.x;  // one float4 each
    if (i4 >= n * (FOUT / 4)) return;
    int row = i4 >> 4;
    float s = g_erowsum[row];
    if (s == 0.f) s = 1.f;
    float inv = 1.f / s;
    float4 v = ((const float4*)g_hprime)[i4];
    v.x *= inv; v.y *= inv; v.z *= inv; v.w *= inv;
    v.x = v.x > 0.f ? v.x : expm1f(v.x);
    v.y = v.y > 0.f ? v.y : expm1f(v.y);
    v.z = v.z > 0.f ? v.z : expm1f(v.z);
    v.w = v.w > 0.f ? v.w : expm1f(v.w);
    ((float4*)out)[i4] = v;
}

// ---------------- tail: attention + edge copy ----------------
__global__ void k_tail(const int* __restrict__ edge,
                       float* __restrict__ out_edges,
                       float* __restrict__ out_att, int E) {
    int e = blockIdx.x * blockDim.x + threadIdx.x;
    if (e >= E) return;
    int dst = edge[e];
    int src = edge[E + e];
    out_edges[e] = (float)dst;
    out_edges[E + e] = (float)src;
    float s = g_erowsum[dst];
    if (s == 0.f) s = 1.f;
    out_att[e] = g_edge_e[e] / s;
}

extern "C" void kernel_launch(void* const* d_in, const int* in_sizes, int n_in,
                              void* d_out, int out_size) {
    const float* input      = (const float*)d_in[0];
    const float* p_h        = (const float*)d_in[1];
    const float* new_h      = (const float*)d_in[2];
    const int*   edge       = (const int*)d_in[3];
    const int*   edge_col   = (const int*)d_in[4];
    const int*   row_i      = (const int*)d_in[5];
    const int*   row_resort = (const int*)d_in[6];
    const float* W          = (const float*)d_in[8];
    const float* a1         = (const float*)d_in[9];
    const float* a2         = (const float*)d_in[10];

    int N = in_sizes[0] / FIN;
    int E = in_sizes[3] / 2;
    const int* edge0 = edge;
    const int* edge1 = edge + E;
    float* out = (float*)d_out;

    long n64 = (long)N * FOUT;
    int full = (out_size >= (int)(n64 + 2L * E + E)) ? 1 : 0;
    float* out_edges = full ? out + n64 : nullptr;
    float* out_att   = full ? out + n64 + 2L * E : nullptr;

    const int T = 256;
    // launch order keeps k_gemm at #4 (the ncu-profiled launch)
    k_zero<<<(N * 16 + T - 1) / T, T>>>(N);
    k_vec<<<1, 128>>>(W, a1, a2);
    k_dots<<<(((N + 1) / 2) * 32 + T - 1) / T, T>>>(input, p_h, new_h, N);
    k_gemm<<<(N + 127) / 128, 512>>>(input, W, N);

    k_col1<<<(N + T - 1) / T, T>>>(edge_col, row_i, N);
    k_col2<<<(N + T - 1) / T, T>>>(row_i, N);
    k_col3<<<(N + T - 1) / T, T>>>(row_i, N);

    k_edge<<<(E * 16 + T - 1) / T, T>>>(edge0, edge1, row_resort, E);

    k_final<<<((N * FOUT / 4) + T - 1) / T, T>>>(out, N);
    if (full) {
        k_tail<<<(E + T - 1) / T, T>>>(edge, out_edges, out_att, E);
    }
}

// round 12
// speedup vs baseline: 1.1134x; 1.1134x over previous
#include <cuda_runtime.h>
#include <cuda_fp16.h>
#include <mma.h>
#include <math.h>

using namespace nvcuda;

#define NMAX 50000
#define NPAD 50176                 // padded rows so wmma tail stores stay in-bounds
#define EMAX 1600000
#define FIN  128
#define FOUT 64
#define ALPHA 0.2f

// ---------------- scratch (device globals; no allocation) ----------------
__device__ float g_h[NPAD * FOUT];       // h = input @ W (fp32; padded tail)
__device__ float g_hprime[NMAX * FOUT];  // segment sum accumulator
__device__ float g_hcol[NMAX];           // h . a1l  (= input . (W a1l))
__device__ float g_ha2r[NMAX];           // h . a2r
__device__ float g_pha1r[NMAX];          // p_h . (W a1r)
__device__ float g_nha2l[NMAX];          // new_h . (W a2l)
__device__ float g_ecsm[NMAX];           // edge_col_e -> ex -> softmax result
__device__ float g_segmax[NMAX];
__device__ float g_segsum[NMAX];
__device__ float g_erowsum[NMAX];
__device__ float g_einv[NMAX];
__device__ float g_edge_e[EMAX];
__device__ float g_v1[FIN], g_v2[FIN], g_v3[FIN], g_v4[FIN];

// ---------------- small vectors: v = W @ a-halves ----------------
__global__ void k_vec(const float* __restrict__ W,
                      const float* __restrict__ a1,
                      const float* __restrict__ a2) {
    int k = threadIdx.x;  // 128 threads
    float s1 = 0.f, s2 = 0.f, s3 = 0.f, s4 = 0.f;
#pragma unroll 8
    for (int j = 0; j < FOUT; j++) {
        float w = W[k * FOUT + j];
        s1 += w * a1[j];
        s2 += w * a1[FOUT + j];
        s3 += w * a2[j];
        s4 += w * a2[FOUT + j];
    }
    g_v1[k] = s1; g_v2[k] = s2; g_v3[k] = s3; g_v4[k] = s4;
}

// ---------------- zeroing (graph-replay safe reset) ----------------
__global__ void k_zero_n(int n) {
    int i = blockIdx.x * blockDim.x + threadIdx.x;
    if (i < n) {
        g_segmax[i] = 0.f;
        g_segsum[i] = 0.f;
        g_erowsum[i] = 0.f;
    }
}
__global__ void k_zero_hp(int n4) {  // n4 = N*FOUT/4
    int i = blockIdx.x * blockDim.x + threadIdx.x;
    if (i < n4) ((float4*)g_hprime)[i] = make_float4(0.f, 0.f, 0.f, 0.f);
}

// ---------------- GEMM: h = input @ W via fp16 tensor cores ----------------
// 256 threads = 8 warps (4 row-groups x 2 col-groups). Block tile 64x64 out.
// Full K (128) staged in smem as fp16 in ONE pass -> single __syncthreads,
// maximum GMEM MLP, 8 uninterrupted wmma k-steps. 35.8 KB smem -> ~5 blk/SM.
#define XS_LD 136   // 128 + 8 pad halves; 272 B row stride (16B multiple)
#define WS_LD 72    //  64 + 8 pad halves; 144 B row stride
__global__ void __launch_bounds__(256)
k_gemm(const float* __restrict__ X, const float* __restrict__ W, int n) {
    __shared__ __half Xs[64][XS_LD];   // 17.4 KB  [row][k]
    __shared__ __half Ws[128][WS_LD];  // 18.4 KB  [k][col]
    int tid = threadIdx.x;
    int warp = tid >> 5;
    int wr = warp >> 1;    // 0..3 -> rows wr*16..+15
    int wc = warp & 1;     // 0..1 -> cols wc*32..+31
    long row0 = (long)blockIdx.x * 64;

    // stage X: 64 rows x 128 k = 2048 float4, 8 per thread
#pragma unroll
    for (int i = 0; i < 8; i++) {
        int idx = tid + i * 256;       // 0..2047
        int r = idx >> 5;              // 32 float4 per row
        int k0 = (idx & 31) * 4;
        long row = row0 + r;
        __half2 h0, h1;
        if (row < n) {
            float4 v = *(const float4*)(X + row * FIN + k0);
            h0 = __floats2half2_rn(v.x, v.y);
            h1 = __floats2half2_rn(v.z, v.w);
        } else {
            h0 = __floats2half2_rn(0.f, 0.f);
            h1 = h0;
        }
        __half2* dst = (__half2*)&Xs[r][k0];
        dst[0] = h0; dst[1] = h1;
    }
    // stage W: 128 k x 64 c = 2048 float4, 8 per thread
#pragma unroll
    for (int i = 0; i < 8; i++) {
        int idx = tid + i * 256;       // 0..2047
        int k = idx >> 4;              // 16 float4 per k-row
        int c0 = (idx & 15) * 4;
        float4 v = *(const float4*)(W + (long)k * FOUT + c0);
        __half2* dst = (__half2*)&Ws[k][c0];
        dst[0] = __floats2half2_rn(v.x, v.y);
        dst[1] = __floats2half2_rn(v.z, v.w);
    }
    __syncthreads();

    wmma::fragment<wmma::accumulator, 16, 16, 16, float> acc[2];
    wmma::fill_fragment(acc[0], 0.f);
    wmma::fill_fragment(acc[1], 0.f);
#pragma unroll
    for (int k16 = 0; k16 < FIN; k16 += 16) {
        wmma::fragment<wmma::matrix_a, 16, 16, 16, __half, wmma::row_major> a;
        wmma::fragment<wmma::matrix_b, 16, 16, 16, __half, wmma::row_major> b0, b1;
        wmma::load_matrix_sync(a, &Xs[wr * 16][k16], XS_LD);
        wmma::load_matrix_sync(b0, &Ws[k16][wc * 32], WS_LD);
        wmma::load_matrix_sync(b1, &Ws[k16][wc * 32 + 16], WS_LD);
        wmma::mma_sync(acc[0], a, b0, acc[0]);
        wmma::mma_sync(acc[1], a, b1, acc[1]);
    }
    // store (padding rows absorb the tail; g_h has NPAD rows)
#pragma unroll
    for (int j = 0; j < 2; j++) {
        float* dst = g_h + (row0 + wr * 16) * FOUT + wc * 32 + j * 16;
        wmma::store_matrix_sync(dst, acc[j], FOUT, wmma::mem_row_major);
    }
}

// ---------------- per-row dot products: 2 rows per warp ----------------
__global__ void k_dots(const float* __restrict__ X,
                       const float* __restrict__ P,
                       const float* __restrict__ NH, int n) {
    int warp = (blockIdx.x * blockDim.x + threadIdx.x) >> 5;
    int lane = threadIdx.x & 31;
    int r0 = warp * 2;
    if (r0 >= n) return;
    int r1 = r0 + 1 < n ? r0 + 1 : r0;
    float4 xv0 = ((const float4*)(X + (long)r0 * FIN))[lane];
    float4 pv0 = ((const float4*)(P + (long)r0 * FIN))[lane];
    float4 nv0 = ((const float4*)(NH + (long)r0 * FIN))[lane];
    float4 xv1 = ((const float4*)(X + (long)r1 * FIN))[lane];
    float4 pv1 = ((const float4*)(P + (long)r1 * FIN))[lane];
    float4 nv1 = ((const float4*)(NH + (long)r1 * FIN))[lane];
    float4 v1 = ((const float4*)g_v1)[lane];
    float4 v2 = ((const float4*)g_v2)[lane];
    float4 v3 = ((const float4*)g_v3)[lane];
    float4 v4 = ((const float4*)g_v4)[lane];
    float a0 = xv0.x * v1.x + xv0.y * v1.y + xv0.z * v1.z + xv0.w * v1.w;
    float b0 = xv0.x * v4.x + xv0.y * v4.y + xv0.z * v4.z + xv0.w * v4.w;
    float c0 = pv0.x * v2.x + pv0.y * v2.y + pv0.z * v2.z + pv0.w * v2.w;
    float d0 = nv0.x * v3.x + nv0.y * v3.y + nv0.z * v3.z + nv0.w * v3.w;
    float a1 = xv1.x * v1.x + xv1.y * v1.y + xv1.z * v1.z + xv1.w * v1.w;
    float b1 = xv1.x * v4.x + xv1.y * v4.y + xv1.z * v4.z + xv1.w * v4.w;
    float c1 = pv1.x * v2.x + pv1.y * v2.y + pv1.z * v2.z + pv1.w * v2.w;
    float d1 = nv1.x * v3.x + nv1.y * v3.y + nv1.z * v3.z + nv1.w * v3.w;
#pragma unroll
    for (int o = 16; o > 0; o >>= 1) {
        a0 += __shfl_down_sync(0xFFFFFFFFu, a0, o);
        b0 += __shfl_down_sync(0xFFFFFFFFu, b0, o);
        c0 += __shfl_down_sync(0xFFFFFFFFu, c0, o);
        d0 += __shfl_down_sync(0xFFFFFFFFu, d0, o);
        a1 += __shfl_down_sync(0xFFFFFFFFu, a1, o);
        b1 += __shfl_down_sync(0xFFFFFFFFu, b1, o);
        c1 += __shfl_down_sync(0xFFFFFFFFu, c1, o);
        d1 += __shfl_down_sync(0xFFFFFFFFu, d1, o);
    }
    if (lane == 0) {
        g_hcol[r0] = a0; g_ha2r[r0] = b0; g_pha1r[r0] = c0; g_nha2l[r0] = d0;
        if (r1 != r0) {
            g_hcol[r1] = a1; g_ha2r[r1] = b1; g_pha1r[r1] = c1; g_nha2l[r1] = d1;
        }
    }
}

// ---------------- column softmax passes ----------------
__global__ void k_col1(const int* __restrict__ edge_col0,
                       const int* __restrict__ row_i, int n) {
    int i = blockIdx.x * blockDim.x + threadIdx.x;
    if (i >= n) return;
    float cs = g_hcol[edge_col0[i]] + g_pha1r[i];
    float lr = cs > 0.f ? cs : ALPHA * cs;
    float e = expf(-lr);
    g_ecsm[i] = e;
    atomicMax((int*)&g_segmax[row_i[i]], __float_as_int(e));  // e > 0 always
}
__global__ void k_col2(const int* __restrict__ row_i, int n) {
    int i = blockIdx.x * blockDim.x + threadIdx.x;
    if (i >= n) return;
    float ex = expf(g_ecsm[i] - g_segmax[row_i[i]]);
    g_ecsm[i] = ex;
    atomicAdd(&g_segsum[row_i[i]], ex);
}
__global__ void k_col3(const int* __restrict__ row_i, int n) {
    int i = blockIdx.x * blockDim.x + threadIdx.x;
    if (i >= n) return;
    g_ecsm[i] = g_ecsm[i] / (g_segsum[row_i[i]] + 1e-16f);
}

// ---------------- edge scores + rowsum (1 thread/edge; R10 proven) --------
__global__ void k_edge1(const int* __restrict__ edge0,
                        const int* __restrict__ edge1,
                        const int* __restrict__ row_resort, int E) {
    int e = blockIdx.x * blockDim.x + threadIdx.x;
    if (e >= E) return;
    int rr = row_resort[e];
    float rs = g_nha2l[rr] + g_ha2r[edge1[e]];
    float lr = rs > 0.f ? rs : ALPHA * rs;
    float ee = expf(-lr) * g_ecsm[rr];
    g_edge_e[e] = ee;
    atomicAdd(&g_erowsum[edge0[e]], ee);
}
__global__ void k_rowfix(int n) {
    int i = blockIdx.x * blockDim.x + threadIdx.x;
    if (i >= n) return;
    float s = g_erowsum[i];
    if (s == 0.f) s = 1.f;
    g_einv[i] = 1.f / s;
}

// ---------------- main scatter: h_prime += edge_e * h[edge1] ----------------
// 16 threads per edge, float4 gather + red.global.add.v4.f32 scatter (R10)
__global__ void k_edge2(const int* __restrict__ edge0,
                        const int* __restrict__ edge1,
                        float* __restrict__ att_out, int E, int write_att) {
    int e = (blockIdx.x * blockDim.x + threadIdx.x) >> 4;
    int t = threadIdx.x & 15;
    if (e >= E) return;
    int dst = edge0[e], src = edge1[e];
    float ee = g_edge_e[e];
    float4 hv = *(const float4*)(g_h + (long)src * FOUT + t * 4);
    float4 r;
    r.x = ee * hv.x; r.y = ee * hv.y; r.z = ee * hv.z; r.w = ee * hv.w;
    float* dp = g_hprime + (long)dst * FOUT + t * 4;
    asm volatile("red.global.add.v4.f32 [%0], {%1, %2, %3, %4};"
                 :: "l"(__cvta_generic_to_global(dp)),
                    "f"(r.x), "f"(r.y), "f"(r.z), "f"(r.w)
                 : "memory");
    if (t == 0 && write_att) att_out[e] = ee * g_einv[dst];
}

// ---------------- finalize: out = elu(h_prime / e_rowsum) ----------------
__global__ void k_final(float* __restrict__ out, int n) {
    int i4 = blockIdx.x * blockDim.x + threadIdx.x;  // one float4 each
    if (i4 >= n * (FOUT / 4)) return;
    int row = i4 >> 4;
    float inv = g_einv[row];
    float4 v = ((const float4*)g_hprime)[i4];
    v.x *= inv; v.y *= inv; v.z *= inv; v.w *= inv;
    v.x = v.x > 0.f ? v.x : expm1f(v.x);
    v.y = v.y > 0.f ? v.y : expm1f(v.y);
    v.z = v.z > 0.f ? v.z : expm1f(v.z);
    v.w = v.w > 0.f ? v.w : expm1f(v.w);
    ((float4*)out)[i4] = v;
}

// ---------------- copy edge indices to output as float ----------------
__global__ void k_edgecopy(const int* __restrict__ edge, float* __restrict__ out,
                           int n2e) {
    int i = blockIdx.x * blockDim.x + threadIdx.x;
    if (i < n2e) out[i] = (float)edge[i];
}

extern "C" void kernel_launch(void* const* d_in, const int* in_sizes, int n_in,
                              void* d_out, int out_size) {
    const float* input      = (const float*)d_in[0];
    const float* p_h        = (const float*)d_in[1];
    const float* new_h      = (const float*)d_in[2];
    const int*   edge       = (const int*)d_in[3];
    const int*   edge_col   = (const int*)d_in[4];
    const int*   row_i      = (const int*)d_in[5];
    const int*   row_resort = (const int*)d_in[6];
    const float* W          = (const float*)d_in[8];
    const float* a1         = (const float*)d_in[9];
    const float* a2         = (const float*)d_in[10];

    int N = in_sizes[0] / FIN;
    int E = in_sizes[3] / 2;
    const int* edge0 = edge;
    const int* edge1 = edge + E;
    float* out = (float*)d_out;

    long n64 = (long)N * FOUT;
    int full = (out_size >= (int)(n64 + 2L * E + E)) ? 1 : 0;
    float* out_edges = full ? out + n64 : nullptr;
    float* out_att   = full ? out + n64 + 2L * E : out;  // dummy if !full

    const int T = 256;
    // zero scratch (every call: graph replays); gemm stays launch #4
    k_zero_n<<<(N + T - 1) / T, T>>>(N);
    k_zero_hp<<<((N * FOUT / 4) + T - 1) / T, T>>>(N * FOUT / 4);

    k_vec<<<1, 128>>>(W, a1, a2);
    k_gemm<<<(N + 63) / 64, 256>>>(input, W, N);     // launch #4 -> profiled
    k_dots<<<(((N + 1) / 2) * 32 + T - 1) / T, T>>>(input, p_h, new_h, N);

    k_col1<<<(N + T - 1) / T, T>>>(edge_col, row_i, N);
    k_col2<<<(N + T - 1) / T, T>>>(row_i, N);
    k_col3<<<(N + T - 1) / T, T>>>(row_i, N);

    k_edge1<<<(E + T - 1) / T, T>>>(edge0, edge1, row_resort, E);
    k_rowfix<<<(N + T - 1) / T, T>>>(N);

    k_edge2<<<(E * 16 + T - 1) / T, T>>>(edge0, edge1, out_att, E, full);
    k_final<<<((N * FOUT / 4) + T - 1) / T, T>>>(out, N);
    if (full) {
        k_edgecopy<<<(2 * E + T - 1) / T, T>>>(edge, out_edges, 2 * E);
    }
}

// round 13
// speedup vs baseline: 1.2700x; 1.1406x over previous
#include <cuda_runtime.h>
#include <cuda_fp16.h>
#include <mma.h>
#include <math.h>

using namespace nvcuda;

#define NMAX 50000
#define NPAD 50176                 // padded rows so wmma tail stores stay in-bounds
#define EMAX 1600000
#define FIN  128
#define FOUT 64
#define ALPHA 0.2f

// ---------------- scratch (device globals; no allocation) ----------------
__device__ float g_h[NPAD * FOUT];       // h = input @ W (fp32; padded tail)
__device__ float g_hprime[NMAX * FOUT];  // segment sum accumulator
__device__ float g_hcol[NMAX];           // h . a1l  (= input . (W a1l))
__device__ float g_ha2r[NMAX];           // h . a2r
__device__ float g_pha1r[NMAX];          // p_h . (W a1r)
__device__ float g_nha2l[NMAX];          // new_h . (W a2l)
__device__ float g_ecsm[NMAX];           // edge_col_e -> ex -> softmax result
__device__ float g_segmax[NMAX];
__device__ float g_segsum[NMAX];
__device__ float g_erowsum[NMAX];
__device__ float g_einv[NMAX];
__device__ float g_edge_e[EMAX];
__device__ float g_v1[FIN], g_v2[FIN], g_v3[FIN], g_v4[FIN];

// ---------------- small vectors: v = W @ a-halves ----------------
__global__ void k_vec(const float* __restrict__ W,
                      const float* __restrict__ a1,
                      const float* __restrict__ a2) {
    int k = threadIdx.x;  // 128 threads
    float s1 = 0.f, s2 = 0.f, s3 = 0.f, s4 = 0.f;
#pragma unroll 8
    for (int j = 0; j < FOUT; j++) {
        float w = W[k * FOUT + j];
        s1 += w * a1[j];
        s2 += w * a1[FOUT + j];
        s3 += w * a2[j];
        s4 += w * a2[FOUT + j];
    }
    g_v1[k] = s1; g_v2[k] = s2; g_v3[k] = s3; g_v4[k] = s4;
}

// ---------------- zeroing (graph-replay safe reset) ----------------
__global__ void k_zero_n(int n) {
    int i = blockIdx.x * blockDim.x + threadIdx.x;
    if (i < n) {
        g_segmax[i] = 0.f;
        g_segsum[i] = 0.f;
        g_erowsum[i] = 0.f;
    }
}
__global__ void k_zero_hp(int n4) {  // n4 = N*FOUT/4
    int i = blockIdx.x * blockDim.x + threadIdx.x;
    if (i < n4) ((float4*)g_hprime)[i] = make_float4(0.f, 0.f, 0.f, 0.f);
}

// ---------------- GEMM: h = input @ W via fp16 tensor cores (R12) ----------
#define XS_LD 136   // 128 + 8 pad halves; 272 B row stride (16B multiple)
#define WS_LD 72    //  64 + 8 pad halves; 144 B row stride
__global__ void __launch_bounds__(256)
k_gemm(const float* __restrict__ X, const float* __restrict__ W, int n) {
    __shared__ __half Xs[64][XS_LD];   // 17.4 KB  [row][k]
    __shared__ __half Ws[128][WS_LD];  // 18.4 KB  [k][col]
    int tid = threadIdx.x;
    int warp = tid >> 5;
    int wr = warp >> 1;    // 0..3 -> rows wr*16..+15
    int wc = warp & 1;     // 0..1 -> cols wc*32..+31
    long row0 = (long)blockIdx.x * 64;

    // stage X: 64 rows x 128 k = 2048 float4, 8 per thread
#pragma unroll
    for (int i = 0; i < 8; i++) {
        int idx = tid + i * 256;       // 0..2047
        int r = idx >> 5;              // 32 float4 per row
        int k0 = (idx & 31) * 4;
        long row = row0 + r;
        __half2 h0, h1;
        if (row < n) {
            float4 v = *(const float4*)(X + row * FIN + k0);
            h0 = __floats2half2_rn(v.x, v.y);
            h1 = __floats2half2_rn(v.z, v.w);
        } else {
            h0 = __floats2half2_rn(0.f, 0.f);
            h1 = h0;
        }
        __half2* dst = (__half2*)&Xs[r][k0];
        dst[0] = h0; dst[1] = h1;
    }
    // stage W: 128 k x 64 c = 2048 float4, 8 per thread
#pragma unroll
    for (int i = 0; i < 8; i++) {
        int idx = tid + i * 256;       // 0..2047
        int k = idx >> 4;              // 16 float4 per k-row
        int c0 = (idx & 15) * 4;
        float4 v = *(const float4*)(W + (long)k * FOUT + c0);
        __half2* dst = (__half2*)&Ws[k][c0];
        dst[0] = __floats2half2_rn(v.x, v.y);
        dst[1] = __floats2half2_rn(v.z, v.w);
    }
    __syncthreads();

    wmma::fragment<wmma::accumulator, 16, 16, 16, float> acc[2];
    wmma::fill_fragment(acc[0], 0.f);
    wmma::fill_fragment(acc[1], 0.f);
#pragma unroll
    for (int k16 = 0; k16 < FIN; k16 += 16) {
        wmma::fragment<wmma::matrix_a, 16, 16, 16, __half, wmma::row_major> a;
        wmma::fragment<wmma::matrix_b, 16, 16, 16, __half, wmma::row_major> b0, b1;
        wmma::load_matrix_sync(a, &Xs[wr * 16][k16], XS_LD);
        wmma::load_matrix_sync(b0, &Ws[k16][wc * 32], WS_LD);
        wmma::load_matrix_sync(b1, &Ws[k16][wc * 32 + 16], WS_LD);
        wmma::mma_sync(acc[0], a, b0, acc[0]);
        wmma::mma_sync(acc[1], a, b1, acc[1]);
    }
#pragma unroll
    for (int j = 0; j < 2; j++) {
        float* dst = g_h + (row0 + wr * 16) * FOUT + wc * 32 + j * 16;
        wmma::store_matrix_sync(dst, acc[j], FOUT, wmma::mem_row_major);
    }
}

// ---------------- per-row dot products: 2 rows per warp ----------------
__global__ void k_dots(const float* __restrict__ X,
                       const float* __restrict__ P,
                       const float* __restrict__ NH, int n) {
    int warp = (blockIdx.x * blockDim.x + threadIdx.x) >> 5;
    int lane = threadIdx.x & 31;
    int r0 = warp * 2;
    if (r0 >= n) return;
    int r1 = r0 + 1 < n ? r0 + 1 : r0;
    float4 xv0 = ((const float4*)(X + (long)r0 * FIN))[lane];
    float4 pv0 = ((const float4*)(P + (long)r0 * FIN))[lane];
    float4 nv0 = ((const float4*)(NH + (long)r0 * FIN))[lane];
    float4 xv1 = ((const float4*)(X + (long)r1 * FIN))[lane];
    float4 pv1 = ((const float4*)(P + (long)r1 * FIN))[lane];
    float4 nv1 = ((const float4*)(NH + (long)r1 * FIN))[lane];
    float4 v1 = ((const float4*)g_v1)[lane];
    float4 v2 = ((const float4*)g_v2)[lane];
    float4 v3 = ((const float4*)g_v3)[lane];
    float4 v4 = ((const float4*)g_v4)[lane];
    float a0 = xv0.x * v1.x + xv0.y * v1.y + xv0.z * v1.z + xv0.w * v1.w;
    float b0 = xv0.x * v4.x + xv0.y * v4.y + xv0.z * v4.z + xv0.w * v4.w;
    float c0 = pv0.x * v2.x + pv0.y * v2.y + pv0.z * v2.z + pv0.w * v2.w;
    float d0 = nv0.x * v3.x + nv0.y * v3.y + nv0.z * v3.z + nv0.w * v3.w;
    float a1 = xv1.x * v1.x + xv1.y * v1.y + xv1.z * v1.z + xv1.w * v1.w;
    float b1 = xv1.x * v4.x + xv1.y * v4.y + xv1.z * v4.z + xv1.w * v4.w;
    float c1 = pv1.x * v2.x + pv1.y * v2.y + pv1.z * v2.z + pv1.w * v2.w;
    float d1 = nv1.x * v3.x + nv1.y * v3.y + nv1.z * v3.z + nv1.w * v3.w;
#pragma unroll
    for (int o = 16; o > 0; o >>= 1) {
        a0 += __shfl_down_sync(0xFFFFFFFFu, a0, o);
        b0 += __shfl_down_sync(0xFFFFFFFFu, b0, o);
        c0 += __shfl_down_sync(0xFFFFFFFFu, c0, o);
        d0 += __shfl_down_sync(0xFFFFFFFFu, d0, o);
        a1 += __shfl_down_sync(0xFFFFFFFFu, a1, o);
        b1 += __shfl_down_sync(0xFFFFFFFFu, b1, o);
        c1 += __shfl_down_sync(0xFFFFFFFFu, c1, o);
        d1 += __shfl_down_sync(0xFFFFFFFFu, d1, o);
    }
    if (lane == 0) {
        g_hcol[r0] = a0; g_ha2r[r0] = b0; g_pha1r[r0] = c0; g_nha2l[r0] = d0;
        if (r1 != r0) {
            g_hcol[r1] = a1; g_ha2r[r1] = b1; g_pha1r[r1] = c1; g_nha2l[r1] = d1;
        }
    }
}

// ---------------- column softmax passes ----------------
__global__ void k_col1(const int* __restrict__ edge_col0,
                       const int* __restrict__ row_i, int n) {
    int i = blockIdx.x * blockDim.x + threadIdx.x;
    if (i >= n) return;
    float cs = g_hcol[edge_col0[i]] + g_pha1r[i];
    float lr = cs > 0.f ? cs : ALPHA * cs;
    float e = expf(-lr);
    g_ecsm[i] = e;
    atomicMax((int*)&g_segmax[row_i[i]], __float_as_int(e));  // e > 0 always
}
__global__ void k_col2(const int* __restrict__ row_i, int n) {
    int i = blockIdx.x * blockDim.x + threadIdx.x;
    if (i >= n) return;
    float ex = expf(g_ecsm[i] - g_segmax[row_i[i]]);
    g_ecsm[i] = ex;
    atomicAdd(&g_segsum[row_i[i]], ex);
}
__global__ void k_col3(const int* __restrict__ row_i, int n) {
    int i = blockIdx.x * blockDim.x + threadIdx.x;
    if (i >= n) return;
    g_ecsm[i] = g_ecsm[i] / (g_segsum[row_i[i]] + 1e-16f);
}

// ---------------- edge scores + rowsum (1 thread/edge; proven) ------------
__global__ void k_edge1(const int* __restrict__ edge0,
                        const int* __restrict__ edge1,
                        const int* __restrict__ row_resort, int E) {
    int e = blockIdx.x * blockDim.x + threadIdx.x;
    if (e >= E) return;
    int rr = row_resort[e];
    float rs = g_nha2l[rr] + g_ha2r[edge1[e]];
    float lr = rs > 0.f ? rs : ALPHA * rs;
    float ee = expf(-lr) * g_ecsm[rr];
    g_edge_e[e] = ee;
    atomicAdd(&g_erowsum[edge0[e]], ee);
}
__global__ void k_rowfix(int n) {
    int i = blockIdx.x * blockDim.x + threadIdx.x;
    if (i >= n) return;
    float s = g_erowsum[i];
    if (s == 0.f) s = 1.f;
    g_einv[i] = 1.f / s;
}

// ---------------- main scatter: warp owns 32 edges, shfl-distributed -------
// Lane l loads edge (base+l)'s (dst, src, ee) coalesced; 16 unrolled steps
// handle 2 edges each (one per half-warp) via shfl.idx, issuing the proven
// LDG.128 + red.v4.f32 pair. LSU instrs per 32 edges: 112 -> 37.
__global__ void k_edge2(const int* __restrict__ edge0,
                        const int* __restrict__ edge1,
                        float* __restrict__ att_out, int E, int write_att) {
    int warp = (blockIdx.x * blockDim.x + threadIdx.x) >> 5;
    int lane = threadIdx.x & 31;
    int base = warp * 32;
    if (base >= E) return;
    int e = base + lane;
    bool ok = e < E;
    int d = ok ? edge0[e] : 0;
    int s = ok ? edge1[e] : 0;
    float ee = ok ? g_edge_e[e] : 0.f;
    if (write_att && ok) att_out[e] = ee * g_einv[d];
    int half = lane >> 4;       // 0 or 1
    int t = lane & 15;          // 16B segment of the 256B row
#pragma unroll
    for (int j = 0; j < 16; j++) {
        int srcl = 2 * j + half;
        int sj = __shfl_sync(0xFFFFFFFFu, s, srcl);
        int dj = __shfl_sync(0xFFFFFFFFu, d, srcl);
        float ej = __shfl_sync(0xFFFFFFFFu, ee, srcl);
        float4 hv = *(const float4*)(g_h + (long)sj * FOUT + t * 4);
        float4 r;
        r.x = ej * hv.x; r.y = ej * hv.y; r.z = ej * hv.z; r.w = ej * hv.w;
        float* dp = g_hprime + (long)dj * FOUT + t * 4;
        asm volatile("red.global.add.v4.f32 [%0], {%1, %2, %3, %4};"
                     :: "l"(__cvta_generic_to_global(dp)),
                        "f"(r.x), "f"(r.y), "f"(r.z), "f"(r.w)
                     : "memory");
    }
}

// ---------------- finalize: out = elu(h_prime / e_rowsum) ----------------
__global__ void k_final(float* __restrict__ out, int n) {
    int i4 = blockIdx.x * blockDim.x + threadIdx.x;  // one float4 each
    if (i4 >= n * (FOUT / 4)) return;
    int row = i4 >> 4;
    float inv = g_einv[row];
    float4 v = ((const float4*)g_hprime)[i4];
    v.x *= inv; v.y *= inv; v.z *= inv; v.w *= inv;
    v.x = v.x > 0.f ? v.x : expm1f(v.x);
    v.y = v.y > 0.f ? v.y : expm1f(v.y);
    v.z = v.z > 0.f ? v.z : expm1f(v.z);
    v.w = v.w > 0.f ? v.w : expm1f(v.w);
    ((float4*)out)[i4] = v;
}

// ---------------- copy edge indices to output as float ----------------
__global__ void k_edgecopy(const int* __restrict__ edge, float* __restrict__ out,
                           int n2e) {
    int i = blockIdx.x * blockDim.x + threadIdx.x;
    if (i < n2e) out[i] = (float)edge[i];
}

extern "C" void kernel_launch(void* const* d_in, const int* in_sizes, int n_in,
                              void* d_out, int out_size) {
    const float* input      = (const float*)d_in[0];
    const float* p_h        = (const float*)d_in[1];
    const float* new_h      = (const float*)d_in[2];
    const int*   edge       = (const int*)d_in[3];
    const int*   edge_col   = (const int*)d_in[4];
    const int*   row_i      = (const int*)d_in[5];
    const int*   row_resort = (const int*)d_in[6];
    const float* W          = (const float*)d_in[8];
    const float* a1         = (const float*)d_in[9];
    const float* a2         = (const float*)d_in[10];

    int N = in_sizes[0] / FIN;
    int E = in_sizes[3] / 2;
    const int* edge0 = edge;
    const int* edge1 = edge + E;
    float* out = (float*)d_out;

    long n64 = (long)N * FOUT;
    int full = (out_size >= (int)(n64 + 2L * E + E)) ? 1 : 0;
    float* out_edges = full ? out + n64 : nullptr;
    float* out_att   = full ? out + n64 + 2L * E : out;  // dummy if !full

    const int T = 256;
    // zero scratch (every call: graph replays); gemm stays launch #4
    k_zero_n<<<(N + T - 1) / T, T>>>(N);
    k_zero_hp<<<((N * FOUT / 4) + T - 1) / T, T>>>(N * FOUT / 4);

    k_vec<<<1, 128>>>(W, a1, a2);
    k_gemm<<<(N + 63) / 64, 256>>>(input, W, N);     // launch #4 -> profiled
    k_dots<<<(((N + 1) / 2) * 32 + T - 1) / T, T>>>(input, p_h, new_h, N);

    k_col1<<<(N + T - 1) / T, T>>>(edge_col, row_i, N);
    k_col2<<<(N + T - 1) / T, T>>>(row_i, N);
    k_col3<<<(N + T - 1) / T, T>>>(row_i, N);

    k_edge1<<<(E + T - 1) / T, T>>>(edge0, edge1, row_resort, E);
    k_rowfix<<<(N + T - 1) / T, T>>>(N);

    int nwarps = (E + 31) / 32;
    k_edge2<<<(nwarps * 32 + T - 1) / T, T>>>(edge0, edge1, out_att, E, full);
    k_final<<<((N * FOUT / 4) + T - 1) / T, T>>>(out, N);
    if (full) {
        k_edgecopy<<<(2 * E + T - 1) / T, T>>>(edge, out_edges, 2 * E);
    }
}